// round 15
// baseline (speedup 1.0000x reference)
#include <cuda_runtime.h>
#include <cuda_fp16.h>
#include <cstdint>

// ---------------------------------------------------------------------------
// HQQ grouped GEMM (sm_103 baseline ISA), split pipeline:
//   conv_a:     A fp32 -> fp16 scratch
//   dequant_w:  int4 -> fp16 W; 8 k-rows/thread, 16 streaming code LDGs
//               front-batched (MLP at the per-warp cap)
//   hqq_gemm:   fp16 GEMM, CTA 128x128 (4 warps, warp 64x64), BK=64,
//               3-stage cp.async, 107.5KB smem -> 2 CTAs/SM (R14 core).
// ---------------------------------------------------------------------------

namespace {
constexpr int T_TOKENS = 4096;
constexpr int K_DIM    = 2048;
constexpr int N_DIM    = 5632;
constexpr int N_EXP    = 8;
constexpr int M_PER_E  = T_TOKENS / N_EXP;   // 512

constexpr int BM = 128, BN = 128, BK = 64;
constexpr int THREADS  = 128;                // 4 warps: 2(m) x 2(n), warp 64x64
constexpr int NKT      = K_DIM / BK;         // 32
constexpr int STAGES   = 3;

constexpr int AS_STRIDE = BK + 8;            // 72 halves = 144B rows
constexpr int BS_STRIDE = BN + 8;            // 136 halves = 272B rows
constexpr int A_STAGE_B = BM * AS_STRIDE * 2;   // 18432 B
constexpr int B_STAGE_B = BK * BS_STRIDE * 2;   // 17408 B
constexpr int SM_B_OFF  = STAGES * A_STAGE_B;   // 55296
constexpr int SMEM_TOTAL = SM_B_OFF + STAGES * B_STAGE_B;  // 107520 B  (2/SM)
}

__device__ __half g_Ah[(size_t)T_TOKENS * K_DIM];          // 16.8 MB
__device__ __half g_Wh[(size_t)N_EXP * K_DIM * N_DIM];     // 184.5 MB

__device__ __forceinline__ unsigned smem_addr(const void* p) {
    return (unsigned)__cvta_generic_to_shared(p);
}
__device__ __forceinline__ void cp_async16(unsigned dst, const void* src) {
    asm volatile("cp.async.cg.shared.global [%0], [%1], 16;\n" :: "r"(dst), "l"(src));
}
__device__ __forceinline__ void cp_commit() {
    asm volatile("cp.async.commit_group;\n" ::: "memory");
}
__device__ __forceinline__ void cp_wait1() {
    asm volatile("cp.async.wait_group 1;\n" ::: "memory");
}
__device__ __forceinline__ void cp_wait0() {
    asm volatile("cp.async.wait_group 0;\n" ::: "memory");
}
__device__ __forceinline__ void ldsm_x4(unsigned addr, uint32_t& r0, uint32_t& r1,
                                        uint32_t& r2, uint32_t& r3) {
    asm volatile("ldmatrix.sync.aligned.m8n8.x4.shared.b16 {%0,%1,%2,%3}, [%4];\n"
                 : "=r"(r0), "=r"(r1), "=r"(r2), "=r"(r3) : "r"(addr));
}
__device__ __forceinline__ void ldsm_x4_trans(unsigned addr, uint32_t& r0, uint32_t& r1,
                                              uint32_t& r2, uint32_t& r3) {
    asm volatile("ldmatrix.sync.aligned.m8n8.x4.trans.shared.b16 {%0,%1,%2,%3}, [%4];\n"
                 : "=r"(r0), "=r"(r1), "=r"(r2), "=r"(r3) : "r"(addr));
}
__device__ __forceinline__ void mma16816(float c[4], const uint32_t a[4], const uint32_t b[2]) {
    asm volatile("mma.sync.aligned.m16n8k16.row.col.f32.f16.f16.f32 "
                 "{%0,%1,%2,%3}, {%4,%5,%6,%7}, {%8,%9}, {%0,%1,%2,%3};\n"
                 : "+f"(c[0]), "+f"(c[1]), "+f"(c[2]), "+f"(c[3])
                 : "r"(a[0]), "r"(a[1]), "r"(a[2]), "r"(a[3]),
                   "r"(b[0]), "r"(b[1]));
}

// ---------------------------------------------------------------------------
// Kernel 1: A fp32 -> fp16
// ---------------------------------------------------------------------------
__global__ void __launch_bounds__(256) conv_a(const float* __restrict__ inp) {
    size_t i = ((size_t)blockIdx.x * 256 + threadIdx.x) * 8;
    float4 f0 = *(const float4*)(inp + i);
    float4 f1 = *(const float4*)(inp + i + 4);
    __half2 h[4];
    h[0] = __floats2half2_rn(f0.x, f0.y);
    h[1] = __floats2half2_rn(f0.z, f0.w);
    h[2] = __floats2half2_rn(f1.x, f1.y);
    h[3] = __floats2half2_rn(f1.z, f1.w);
    *(uint4*)(g_Ah + i) = *(const uint4*)h;
}

// ---------------------------------------------------------------------------
// Kernel 2: int4 codes -> fp16 W.
// One thread: 8 n-cols x 8 k-rows (single scale group, 8|64).
// 16 streaming (.cs) int4 code loads + 4 scale loads, all front-batched.
// ---------------------------------------------------------------------------
__global__ void __launch_bounds__(256) dequant_w(const int* __restrict__ wq,
                                                 const float* __restrict__ sz) {
    const int gid = blockIdx.x * 256 + threadIdx.x;
    const int n8   = gid % (N_DIM / 8);
    const int rest = gid / (N_DIM / 8);
    const int k8   = rest % (K_DIM / 8);
    const int e    = rest / (K_DIM / 8);
    const int k0   = k8 * 8;
    const int n    = n8 * 8;

    const int* wp = wq + ((size_t)e * K_DIM + k0) * N_DIM + n;
    const float* szp = sz + ((size_t)e * (K_DIM / 64) * N_DIM
                             + (size_t)(k0 >> 6) * N_DIM + n) * 2;

    // ---- front-batched loads: 16 streaming code int4 + 4 scale float4 ----
    int4 c[8][2];
#pragma unroll
    for (int j = 0; j < 8; ++j) {
        c[j][0] = __ldcs((const int4*)(wp + (size_t)j * N_DIM));
        c[j][1] = __ldcs((const int4*)(wp + (size_t)j * N_DIM + 4));
    }
    float4 q0 = *(const float4*)(szp);
    float4 q1 = *(const float4*)(szp + 4);
    float4 q2 = *(const float4*)(szp + 8);
    float4 q3 = *(const float4*)(szp + 12);

    float s[8], za[8];
    s[0]=q0.x; za[0]=fmaf(-8.f,q0.x,q0.y);  s[1]=q0.z; za[1]=fmaf(-8.f,q0.z,q0.w);
    s[2]=q1.x; za[2]=fmaf(-8.f,q1.x,q1.y);  s[3]=q1.z; za[3]=fmaf(-8.f,q1.z,q1.w);
    s[4]=q2.x; za[4]=fmaf(-8.f,q2.x,q2.y);  s[5]=q2.z; za[5]=fmaf(-8.f,q2.z,q2.w);
    s[6]=q3.x; za[6]=fmaf(-8.f,q3.x,q3.y);  s[7]=q3.z; za[7]=fmaf(-8.f,q3.z,q3.w);

    __half* op = g_Wh + ((size_t)e * K_DIM + k0) * N_DIM + n;
#pragma unroll
    for (int j = 0; j < 8; ++j) {
        __half2 h[4];
        h[0] = __floats2half2_rn(fmaf((float)c[j][0].x, s[0], za[0]),
                                 fmaf((float)c[j][0].y, s[1], za[1]));
        h[1] = __floats2half2_rn(fmaf((float)c[j][0].z, s[2], za[2]),
                                 fmaf((float)c[j][0].w, s[3], za[3]));
        h[2] = __floats2half2_rn(fmaf((float)c[j][1].x, s[4], za[4]),
                                 fmaf((float)c[j][1].y, s[5], za[5]));
        h[3] = __floats2half2_rn(fmaf((float)c[j][1].z, s[6], za[6]),
                                 fmaf((float)c[j][1].w, s[7], za[7]));
        *(uint4*)(op + (size_t)j * N_DIM) = *(const uint4*)h;
    }
}

// ---------------------------------------------------------------------------
// Kernel 3: fp16 GEMM, CTA 128x128, 2 CTAs/SM, 3-stage cp.async (R14 core)
// ---------------------------------------------------------------------------
__global__ void __launch_bounds__(THREADS, 2)
hqq_gemm(float* __restrict__ out)
{
    extern __shared__ __align__(16) char smem[];

    const int bn = blockIdx.x;   // 0..43
    const int bm = blockIdx.y;   // 0..3
    const int e  = blockIdx.z;   // 0..7

    const int tid  = threadIdx.x;
    const int lane = tid & 31;
    const int warp = tid >> 5;   // 0..3
    const int wm   = warp >> 1;  // 0..1
    const int wn   = warp & 1;   // 0..1

    const int rowBase = e * M_PER_E + bm * BM;
    const int colBase = bn * BN;

    // ---- cp.async mappings ----
    const int a_row = tid >> 3, a_slot = tid & 7;
    const __half* a_src = g_Ah + (size_t)(rowBase + a_row) * K_DIM + a_slot * 8;
    const unsigned a_dst = smem_addr(smem) + a_row * (AS_STRIDE * 2) + a_slot * 16;
    const int b_row = tid >> 4, b_slot = tid & 15;
    const __half* b_src = g_Wh + ((size_t)e * K_DIM + b_row) * N_DIM + colBase + b_slot * 8;
    const unsigned b_dst = smem_addr(smem) + SM_B_OFF + b_row * (BS_STRIDE * 2) + b_slot * 16;

    auto cpStage = [&](int stg, int kt) {
        const unsigned ad = a_dst + stg * A_STAGE_B;
        const __half*  as = a_src + kt * BK;
#pragma unroll
        for (int j = 0; j < 8; ++j)
            cp_async16(ad + j * 16 * (AS_STRIDE * 2), as + (size_t)j * 16 * K_DIM);
        const unsigned bd = b_dst + stg * B_STAGE_B;
        const __half*  bs = b_src + (size_t)kt * BK * N_DIM;
#pragma unroll
        for (int j = 0; j < 8; ++j)
            cp_async16(bd + j * 8 * (BS_STRIDE * 2), bs + (size_t)j * 8 * N_DIM);
        cp_commit();
    };

    float acc[4][8][4];
#pragma unroll
    for (int mi = 0; mi < 4; ++mi)
#pragma unroll
        for (int ni = 0; ni < 8; ++ni)
#pragma unroll
            for (int j = 0; j < 4; ++j) acc[mi][ni][j] = 0.f;

    const int a_lrow = wm * 64 + (lane & 15);
    const int a_lcol = (lane >> 4) * 8;
    const int b_lrow = lane & 15;
    const int b_lcol = (lane >> 4) * 8;
    const int b_ncol = wn * 64;

    auto compute = [&](int stg) {
        const __half* Ab = (const __half*)(smem + stg * A_STAGE_B);
        const __half* Bb = (const __half*)(smem + SM_B_OFF + stg * B_STAGE_B);
#pragma unroll
        for (int s = 0; s < 4; ++s) {
            uint32_t af[4][4];
#pragma unroll
            for (int mi = 0; mi < 4; ++mi) {
                unsigned addr = smem_addr(Ab + (a_lrow + mi * 16) * AS_STRIDE + s * 16 + a_lcol);
                ldsm_x4(addr, af[mi][0], af[mi][1], af[mi][2], af[mi][3]);
            }
            uint32_t bf[8][2];
#pragma unroll
            for (int j = 0; j < 4; ++j) {
                unsigned addr = smem_addr(Bb + (s * 16 + b_lrow) * BS_STRIDE
                                          + b_ncol + j * 16 + b_lcol);
                ldsm_x4_trans(addr, bf[2*j][0], bf[2*j][1], bf[2*j+1][0], bf[2*j+1][1]);
            }
#pragma unroll
            for (int mi = 0; mi < 4; ++mi)
#pragma unroll
                for (int ni = 0; ni < 8; ++ni)
                    mma16816(acc[mi][ni], af[mi], bf[ni]);
        }
    };

    cpStage(0, 0);
    cpStage(1, 1);

#pragma unroll 1
    for (int kt = 0; kt < NKT; ++kt) {
        const int stg = kt % STAGES;
        if (kt + 1 < NKT) cp_wait1(); else cp_wait0();
        __syncthreads();
        if (kt + 2 < NKT) cpStage((kt + 2) % STAGES, kt + 2);
        compute(stg);
    }

    const int g  = lane >> 2;
    const int cc = lane & 3;
#pragma unroll
    for (int mi = 0; mi < 4; ++mi) {
#pragma unroll
        for (int ni = 0; ni < 8; ++ni) {
            const int r0  = rowBase + wm * 64 + mi * 16 + g;
            const int col = colBase + wn * 64 + ni * 8 + 2 * cc;
            *(float2*)&out[(size_t)r0 * N_DIM + col]       = make_float2(acc[mi][ni][0], acc[mi][ni][1]);
            *(float2*)&out[(size_t)(r0 + 8) * N_DIM + col] = make_float2(acc[mi][ni][2], acc[mi][ni][3]);
        }
    }
}

// ---------------------------------------------------------------------------
extern "C" void kernel_launch(void* const* d_in, const int* in_sizes, int n_in,
                              void* d_out, int out_size) {
    (void)in_sizes; (void)n_in; (void)out_size;
    const float* inp = (const float*)d_in[0];
    // d_in[1] = tokens_per_expert: balanced & contiguous by construction
    const int*   wq  = (const int*)d_in[2];
    const float* sz  = (const float*)d_in[3];
    float* out = (float*)d_out;

    static bool attr_set = false;
    if (!attr_set) {
        cudaFuncSetAttribute(hqq_gemm, cudaFuncAttributeMaxDynamicSharedMemorySize, SMEM_TOTAL);
        attr_set = true;
    }

    conv_a<<<(T_TOKENS * K_DIM) / (256 * 8), 256>>>(inp);
    dequant_w<<<(N_EXP * (K_DIM / 8) * (N_DIM / 8)) / 256, 256>>>(wq, sz);
    dim3 grid(N_DIM / BN, M_PER_E / BM, N_EXP);   // (44, 4, 8)
    hqq_gemm<<<grid, THREADS, SMEM_TOTAL>>>(out);
}

// round 16
// speedup vs baseline: 1.0655x; 1.0655x over previous
#include <cuda_runtime.h>
#include <cuda_fp16.h>
#include <cstdint>

// ---------------------------------------------------------------------------
// HQQ grouped GEMM (sm_103 baseline ISA), split pipeline (R14 core):
//   prep:      fused [A fp32->fp16 conversion | int4->fp16 W dequant];
//              dequant experts processed in REVERSE order so expert 0 is
//              written last (L2-hot when the GEMM starts reading it).
//   hqq_gemm:  fp16 GEMM, CTA 128x128 (4 warps, warp 64x64), BK=64,
//              3-stage cp.async, 107.5KB smem -> 2 CTAs/SM.
// ---------------------------------------------------------------------------

namespace {
constexpr int T_TOKENS = 4096;
constexpr int K_DIM    = 2048;
constexpr int N_DIM    = 5632;
constexpr int N_EXP    = 8;
constexpr int M_PER_E  = T_TOKENS / N_EXP;   // 512

constexpr int BM = 128, BN = 128, BK = 64;
constexpr int THREADS  = 128;                // 4 warps: 2(m) x 2(n), warp 64x64
constexpr int NKT      = K_DIM / BK;         // 32
constexpr int STAGES   = 3;

constexpr int AS_STRIDE = BK + 8;            // 72 halves = 144B rows
constexpr int BS_STRIDE = BN + 8;            // 136 halves = 272B rows
constexpr int A_STAGE_B = BM * AS_STRIDE * 2;   // 18432 B
constexpr int B_STAGE_B = BK * BS_STRIDE * 2;   // 17408 B
constexpr int SM_B_OFF  = STAGES * A_STAGE_B;   // 55296
constexpr int SMEM_TOTAL = SM_B_OFF + STAGES * B_STAGE_B;  // 107520 B  (2/SM)

constexpr int CONV_BLOCKS = (T_TOKENS * K_DIM) / (256 * 8);        // 4096
constexpr int DEQ_BLOCKS  = (N_EXP * (K_DIM / 4) * (N_DIM / 8)) / 256;  // 11264
}

__device__ __half g_Ah[(size_t)T_TOKENS * K_DIM];          // 16.8 MB
__device__ __half g_Wh[(size_t)N_EXP * K_DIM * N_DIM];     // 184.5 MB

__device__ __forceinline__ unsigned smem_addr(const void* p) {
    return (unsigned)__cvta_generic_to_shared(p);
}
__device__ __forceinline__ void cp_async16(unsigned dst, const void* src) {
    asm volatile("cp.async.cg.shared.global [%0], [%1], 16;\n" :: "r"(dst), "l"(src));
}
__device__ __forceinline__ void cp_commit() {
    asm volatile("cp.async.commit_group;\n" ::: "memory");
}
__device__ __forceinline__ void cp_wait1() {
    asm volatile("cp.async.wait_group 1;\n" ::: "memory");
}
__device__ __forceinline__ void cp_wait0() {
    asm volatile("cp.async.wait_group 0;\n" ::: "memory");
}
__device__ __forceinline__ void ldsm_x4(unsigned addr, uint32_t& r0, uint32_t& r1,
                                        uint32_t& r2, uint32_t& r3) {
    asm volatile("ldmatrix.sync.aligned.m8n8.x4.shared.b16 {%0,%1,%2,%3}, [%4];\n"
                 : "=r"(r0), "=r"(r1), "=r"(r2), "=r"(r3) : "r"(addr));
}
__device__ __forceinline__ void ldsm_x4_trans(unsigned addr, uint32_t& r0, uint32_t& r1,
                                              uint32_t& r2, uint32_t& r3) {
    asm volatile("ldmatrix.sync.aligned.m8n8.x4.trans.shared.b16 {%0,%1,%2,%3}, [%4];\n"
                 : "=r"(r0), "=r"(r1), "=r"(r2), "=r"(r3) : "r"(addr));
}
__device__ __forceinline__ void mma16816(float c[4], const uint32_t a[4], const uint32_t b[2]) {
    asm volatile("mma.sync.aligned.m16n8k16.row.col.f32.f16.f16.f32 "
                 "{%0,%1,%2,%3}, {%4,%5,%6,%7}, {%8,%9}, {%0,%1,%2,%3};\n"
                 : "+f"(c[0]), "+f"(c[1]), "+f"(c[2]), "+f"(c[3])
                 : "r"(a[0]), "r"(a[1]), "r"(a[2]), "r"(a[3]),
                   "r"(b[0]), "r"(b[1]));
}

// ---------------------------------------------------------------------------
// Kernel 1: fused prep. Blocks [0, CONV_BLOCKS): A fp32->fp16.
// Blocks [CONV_BLOCKS, ...): W dequant, experts in reverse order.
// ---------------------------------------------------------------------------
__global__ void __launch_bounds__(256) prep(const float* __restrict__ inp,
                                            const int* __restrict__ wq,
                                            const float* __restrict__ sz) {
    if (blockIdx.x < CONV_BLOCKS) {
        size_t i = ((size_t)blockIdx.x * 256 + threadIdx.x) * 8;
        float4 f0 = *(const float4*)(inp + i);
        float4 f1 = *(const float4*)(inp + i + 4);
        __half2 h[4];
        h[0] = __floats2half2_rn(f0.x, f0.y);
        h[1] = __floats2half2_rn(f0.z, f0.w);
        h[2] = __floats2half2_rn(f1.x, f1.y);
        h[3] = __floats2half2_rn(f1.z, f1.w);
        *(uint4*)(g_Ah + i) = *(const uint4*)h;
        return;
    }

    // ---- dequant: one thread = 8 n-cols x 4 k-rows ----
    const int gid = (blockIdx.x - CONV_BLOCKS) * 256 + threadIdx.x;
    const int n8   = gid % (N_DIM / 8);
    const int rest = gid / (N_DIM / 8);
    const int kq   = rest % (K_DIM / 4);
    const int e    = (N_EXP - 1) - rest / (K_DIM / 4);   // reverse: expert 0 last
    const int k0   = kq * 4;
    const int n    = n8 * 8;

    const int* wp = wq + ((size_t)e * K_DIM + k0) * N_DIM + n;
    const float* szp = sz + ((size_t)e * (K_DIM / 64) * N_DIM
                             + (size_t)(k0 >> 6) * N_DIM + n) * 2;

    int4 c[4][2];
#pragma unroll
    for (int j = 0; j < 4; ++j) {
        c[j][0] = *(const int4*)(wp + (size_t)j * N_DIM);
        c[j][1] = *(const int4*)(wp + (size_t)j * N_DIM + 4);
    }
    float4 q0 = *(const float4*)(szp);
    float4 q1 = *(const float4*)(szp + 4);
    float4 q2 = *(const float4*)(szp + 8);
    float4 q3 = *(const float4*)(szp + 12);

    float s[8], za[8];
    s[0]=q0.x; za[0]=fmaf(-8.f,q0.x,q0.y);  s[1]=q0.z; za[1]=fmaf(-8.f,q0.z,q0.w);
    s[2]=q1.x; za[2]=fmaf(-8.f,q1.x,q1.y);  s[3]=q1.z; za[3]=fmaf(-8.f,q1.z,q1.w);
    s[4]=q2.x; za[4]=fmaf(-8.f,q2.x,q2.y);  s[5]=q2.z; za[5]=fmaf(-8.f,q2.z,q2.w);
    s[6]=q3.x; za[6]=fmaf(-8.f,q3.x,q3.y);  s[7]=q3.z; za[7]=fmaf(-8.f,q3.z,q3.w);

    __half* op = g_Wh + ((size_t)e * K_DIM + k0) * N_DIM + n;
#pragma unroll
    for (int j = 0; j < 4; ++j) {
        __half2 h[4];
        h[0] = __floats2half2_rn(fmaf((float)c[j][0].x, s[0], za[0]),
                                 fmaf((float)c[j][0].y, s[1], za[1]));
        h[1] = __floats2half2_rn(fmaf((float)c[j][0].z, s[2], za[2]),
                                 fmaf((float)c[j][0].w, s[3], za[3]));
        h[2] = __floats2half2_rn(fmaf((float)c[j][1].x, s[4], za[4]),
                                 fmaf((float)c[j][1].y, s[5], za[5]));
        h[3] = __floats2half2_rn(fmaf((float)c[j][1].z, s[6], za[6]),
                                 fmaf((float)c[j][1].w, s[7], za[7]));
        *(uint4*)(op + (size_t)j * N_DIM) = *(const uint4*)h;
    }
}

// ---------------------------------------------------------------------------
// Kernel 2: fp16 GEMM, CTA 128x128, 2 CTAs/SM, 3-stage cp.async (R14 core)
// ---------------------------------------------------------------------------
__global__ void __launch_bounds__(THREADS, 2)
hqq_gemm(float* __restrict__ out)
{
    extern __shared__ __align__(16) char smem[];

    const int bn = blockIdx.x;   // 0..43
    const int bm = blockIdx.y;   // 0..3
    const int e  = blockIdx.z;   // 0..7

    const int tid  = threadIdx.x;
    const int lane = tid & 31;
    const int warp = tid >> 5;   // 0..3
    const int wm   = warp >> 1;  // 0..1
    const int wn   = warp & 1;   // 0..1

    const int rowBase = e * M_PER_E + bm * BM;
    const int colBase = bn * BN;

    const int a_row = tid >> 3, a_slot = tid & 7;
    const __half* a_src = g_Ah + (size_t)(rowBase + a_row) * K_DIM + a_slot * 8;
    const unsigned a_dst = smem_addr(smem) + a_row * (AS_STRIDE * 2) + a_slot * 16;
    const int b_row = tid >> 4, b_slot = tid & 15;
    const __half* b_src = g_Wh + ((size_t)e * K_DIM + b_row) * N_DIM + colBase + b_slot * 8;
    const unsigned b_dst = smem_addr(smem) + SM_B_OFF + b_row * (BS_STRIDE * 2) + b_slot * 16;

    auto cpStage = [&](int stg, int kt) {
        const unsigned ad = a_dst + stg * A_STAGE_B;
        const __half*  as = a_src + kt * BK;
#pragma unroll
        for (int j = 0; j < 8; ++j)
            cp_async16(ad + j * 16 * (AS_STRIDE * 2), as + (size_t)j * 16 * K_DIM);
        const unsigned bd = b_dst + stg * B_STAGE_B;
        const __half*  bs = b_src + (size_t)kt * BK * N_DIM;
#pragma unroll
        for (int j = 0; j < 8; ++j)
            cp_async16(bd + j * 8 * (BS_STRIDE * 2), bs + (size_t)j * 8 * N_DIM);
        cp_commit();
    };

    float acc[4][8][4];
#pragma unroll
    for (int mi = 0; mi < 4; ++mi)
#pragma unroll
        for (int ni = 0; ni < 8; ++ni)
#pragma unroll
            for (int j = 0; j < 4; ++j) acc[mi][ni][j] = 0.f;

    const int a_lrow = wm * 64 + (lane & 15);
    const int a_lcol = (lane >> 4) * 8;
    const int b_lrow = lane & 15;
    const int b_lcol = (lane >> 4) * 8;
    const int b_ncol = wn * 64;

    auto compute = [&](int stg) {
        const __half* Ab = (const __half*)(smem + stg * A_STAGE_B);
        const __half* Bb = (const __half*)(smem + SM_B_OFF + stg * B_STAGE_B);
#pragma unroll
        for (int s = 0; s < 4; ++s) {
            uint32_t af[4][4];
#pragma unroll
            for (int mi = 0; mi < 4; ++mi) {
                unsigned addr = smem_addr(Ab + (a_lrow + mi * 16) * AS_STRIDE + s * 16 + a_lcol);
                ldsm_x4(addr, af[mi][0], af[mi][1], af[mi][2], af[mi][3]);
            }
            uint32_t bf[8][2];
#pragma unroll
            for (int j = 0; j < 4; ++j) {
                unsigned addr = smem_addr(Bb + (s * 16 + b_lrow) * BS_STRIDE
                                          + b_ncol + j * 16 + b_lcol);
                ldsm_x4_trans(addr, bf[2*j][0], bf[2*j][1], bf[2*j+1][0], bf[2*j+1][1]);
            }
#pragma unroll
            for (int mi = 0; mi < 4; ++mi)
#pragma unroll
                for (int ni = 0; ni < 8; ++ni)
                    mma16816(acc[mi][ni], af[mi], bf[ni]);
        }
    };

    cpStage(0, 0);
    cpStage(1, 1);

#pragma unroll 1
    for (int kt = 0; kt < NKT; ++kt) {
        const int stg = kt % STAGES;
        if (kt + 1 < NKT) cp_wait1(); else cp_wait0();
        __syncthreads();
        if (kt + 2 < NKT) cpStage((kt + 2) % STAGES, kt + 2);
        compute(stg);
    }

    const int g  = lane >> 2;
    const int cc = lane & 3;
#pragma unroll
    for (int mi = 0; mi < 4; ++mi) {
#pragma unroll
        for (int ni = 0; ni < 8; ++ni) {
            const int r0  = rowBase + wm * 64 + mi * 16 + g;
            const int col = colBase + wn * 64 + ni * 8 + 2 * cc;
            *(float2*)&out[(size_t)r0 * N_DIM + col]       = make_float2(acc[mi][ni][0], acc[mi][ni][1]);
            *(float2*)&out[(size_t)(r0 + 8) * N_DIM + col] = make_float2(acc[mi][ni][2], acc[mi][ni][3]);
        }
    }
}

// ---------------------------------------------------------------------------
extern "C" void kernel_launch(void* const* d_in, const int* in_sizes, int n_in,
                              void* d_out, int out_size) {
    (void)in_sizes; (void)n_in; (void)out_size;
    const float* inp = (const float*)d_in[0];
    // d_in[1] = tokens_per_expert: balanced & contiguous by construction
    const int*   wq  = (const int*)d_in[2];
    const float* sz  = (const float*)d_in[3];
    float* out = (float*)d_out;

    static bool attr_set = false;
    if (!attr_set) {
        cudaFuncSetAttribute(hqq_gemm, cudaFuncAttributeMaxDynamicSharedMemorySize, SMEM_TOTAL);
        attr_set = true;
    }

    prep<<<CONV_BLOCKS + DEQ_BLOCKS, 256>>>(inp, wq, sz);
    dim3 grid(N_DIM / BN, M_PER_E / BM, N_EXP);   // (44, 4, 8)
    hqq_gemm<<<grid, THREADS, SMEM_TOTAL>>>(out);
}